// round 13
// baseline (speedup 1.0000x reference)
#include <cuda_runtime.h>
#include <cuda_bf16.h>
#include <math.h>
#include <stdint.h>

#define E_DIM 512
#define BLROWS 16384
#define NRR 100
#define NPAD 104                        // 13 n-tiles of 8 (cols 100-103 padded)
#define NORM_TERM 10.82490511970208f    // ln(50257)
#define LOG_NR 4.605170185988092f       // ln(100)
#define MROWS 32                        // rows per CTA
#define ASTR 144                        // bf16 tile row stride (72 bf16)
#define ASTAGE (MROWS * ASTR)           // 4608
#define BSTAGE (NPAD * ASTR)            // 14976
#define GSTAGE (MROWS * 256)            // 8192: f32 gather rows
#define NBLK 512

__device__ __align__(16) __nv_bfloat16 g_bn[NPAD * E_DIM];  // bf16 noise table
__device__ float g_part[NBLK];
__device__ int   g_ctr = 0;             // self-resetting (graph-replay safe)

__device__ __forceinline__ uint32_t smem_u32(const void* p) {
    uint32_t a;
    asm("{ .reg .u64 t; cvta.to.shared.u64 t, %1; cvt.u32.u64 %0, t; }" : "=r"(a) : "l"(p));
    return a;
}
__device__ __forceinline__ void cp_async16(uint32_t dst, const void* src) {
    asm volatile("cp.async.cg.shared.global [%0], [%1], 16;" :: "r"(dst), "l"(src) : "memory");
}
#define CP_COMMIT() asm volatile("cp.async.commit_group;" ::: "memory")
#define CP_WAIT2()  asm volatile("cp.async.wait_group 2;" ::: "memory")
__device__ __forceinline__ void ldmatrix_x4(uint32_t& r0, uint32_t& r1,
                                            uint32_t& r2, uint32_t& r3, uint32_t addr) {
    asm volatile("ldmatrix.sync.aligned.m8n8.x4.shared.b16 {%0,%1,%2,%3}, [%4];"
                 : "=r"(r0), "=r"(r1), "=r"(r2), "=r"(r3) : "r"(addr));
}
__device__ __forceinline__ void ldmatrix_x2(uint32_t& r0, uint32_t& r1, uint32_t addr) {
    asm volatile("ldmatrix.sync.aligned.m8n8.x2.shared.b16 {%0,%1}, [%2];"
                 : "=r"(r0), "=r"(r1) : "r"(addr));
}
__device__ __forceinline__ void mma16816(float* d, const uint32_t* a,
                                         uint32_t b0, uint32_t b1) {
    asm volatile("mma.sync.aligned.m16n8k16.row.col.f32.bf16.bf16.f32 "
                 "{%0,%1,%2,%3}, {%4,%5,%6,%7}, {%8,%9}, {%0,%1,%2,%3};"
                 : "+f"(d[0]), "+f"(d[1]), "+f"(d[2]), "+f"(d[3])
                 : "r"(a[0]), "r"(a[1]), "r"(a[2]), "r"(a[3]), "r"(b0), "r"(b1));
}
__device__ __forceinline__ float softplus_exact(float x) {
    return fmaxf(x, 0.0f) + log1pf(expf(-fabsf(x)));
}
__device__ __forceinline__ uint2 cvt_bf16x4(float4 v) {
    __nv_bfloat162 p0 = __float22bfloat162_rn(make_float2(v.x, v.y));
    __nv_bfloat162 p1 = __float22bfloat162_rn(make_float2(v.z, v.w));
    uint2 r;
    r.x = *reinterpret_cast<uint32_t*>(&p0);
    r.y = *reinterpret_cast<uint32_t*>(&p1);
    return r;
}

// ---------------------------------------------------------------------------
__global__ void prep_kernel(const float* __restrict__ emb,
                            const int* __restrict__ nidx) {
    int idx = blockIdx.x * blockDim.x + threadIdx.x;
    if (idx >= NPAD * 128) return;
    int n = idx >> 7, q = idx & 127;
    float4 v = make_float4(0.f, 0.f, 0.f, 0.f);
    if (n < NRR) v = *(const float4*)(emb + (size_t)nidx[n] * E_DIM + q * 4);
    *(uint2*)((char*)g_bn + (size_t)n * 1024 + q * 8) = cvt_bf16x4(v);
}

// ---------------------------------------------------------------------------
// 32-row CTAs, 128 threads, 4 CTAs/SM. Warp w: slab p=w&1 (16 rows), tile
// group h=w>>1 (h=0: 7 tiles, h=1: 6 tiles). 2-stage A/B/G rings.
// Per iter: [c==0: wait] dot+STS A(c) -> commit G(c+2) -> LDG(c+2) -> sync
// -> commit B(c+1) -> wait_group 2 (forces B(c), G(c+1)) -> MMA(c).
// ---------------------------------------------------------------------------
__global__ void __launch_bounds__(128, 4)
mega_kernel(const float* __restrict__ inp,
            const float* __restrict__ emb,
            const float* __restrict__ bias,
            const float* __restrict__ lpn,
            const int*   __restrict__ tgt,
            const int*   __restrict__ nidx,
            float* __restrict__ out) {
    extern __shared__ char dsm[];
    __shared__ float cs[NPAD];
    __shared__ int   s_t[MROWS];
    __shared__ float s_xc[MROWS];
    __shared__ float s_tdot[MROWS];
    __shared__ float s_red[2][MROWS];
    __shared__ float s_fin[MROWS];
    __shared__ int   s_flag;

    const int tid = threadIdx.x;
    const int lane = tid & 31;
    const int warp = tid >> 5;          // 0..3
    const int row0 = blockIdx.x * MROWS;

    const uint32_t db = smem_u32(dsm);
    const uint32_t abase = (db + 127u) & ~127u;
    const uint32_t bbase = abase + 2 * ASTAGE;
    const uint32_t gbase = bbase + 2 * BSTAGE;
    char* ap = dsm + (abase - db);
    char* gp = dsm + (gbase - db);

    if (tid < NPAD) {
        int nv = (tid < NRR) ? nidx[tid] : -1;
        cs[tid] = (tid < NRR) ? (bias[nv] - NORM_TERM - lpn[nv] - LOG_NR) : -1e30f;
    }
    if (tid >= 64 && tid < 64 + MROWS) {
        int r = tid - 64;
        int t = tgt[row0 + r];
        s_t[r] = t;
        s_xc[r] = bias[t] - NORM_TERM - lpn[t] - LOG_NR;
    }
    __syncthreads();

    // ---------------- per-thread layout ----------------
    const int l4 = tid & 15;            // 16B k-slot
    const int rg = tid >> 4;            // 0..7; rows rg+8j, j<4
    const float* ipt = inp + (size_t)(row0 + rg) * E_DIM + l4 * 4;
    const uint32_t asts = (uint32_t)rg * ASTR + l4 * 8;

    const char* embB = (const char*)emb;
    uint32_t gsrc[4], gdst[4];
#pragma unroll
    for (int i = 0; i < 4; i++) {
        int row = rg + 8 * i;
        gsrc[i] = (uint32_t)s_t[row] * 2048u + (uint32_t)l4 * 16u;
        gdst[i] = (uint32_t)row * 256u + (uint32_t)l4 * 16u;
    }

    // B cp.async slots: 832 16B ops over 128 threads (7 per thread, last partial)
    uint32_t bdst[7], bsrc[7];
    int bok[7];
#pragma unroll
    for (int i = 0; i < 7; i++) {
        int idx = tid + 128 * i;
        bok[i] = (idx < NPAD * 8);
        int n = idx >> 3, sl = idx & 7;
        bdst[i] = (uint32_t)n * ASTR + sl * 16;
        bsrc[i] = (uint32_t)n * 1024 + sl * 16;
    }
    const char* bn = (const char*)g_bn;

    // MMA fragment addressing (proven mapping)
    const int p = warp & 1;             // slab
    const int h = warp >> 1;            // tile group
    const int m0 = p * 16;
    const int NT = h ? 6 : 7;           // tiles this warp
    const uint32_t a_woff = (uint32_t)(m0 + (lane & 15)) * ASTR + ((lane >> 4) << 4);
    const uint32_t b_woff = (uint32_t)(h * 56 + (lane & 7) + ((lane >> 4) << 3)) * ASTR
                          + (((lane >> 3) & 1) << 4);
    const uint32_t b2_woff = (uint32_t)(48 + (lane & 7)) * ASTR
                           + (((lane >> 3) & 1) << 4);   // h==0 only

    float acc[7][4];
#pragma unroll
    for (int n = 0; n < 7; n++)
#pragma unroll
        for (int j = 0; j < 4; j++) acc[n][j] = 0.f;
    float tacc[4] = {0.f, 0.f, 0.f, 0.f};

    // ---------------- prologue: commits G(0), G(1), B(0) ----------------
    float4 va[2][4];
#pragma unroll
    for (int s = 0; s < 2; s++)
#pragma unroll
        for (int j = 0; j < 4; j++)
            va[s][j] = *(const float4*)(ipt + s * 64 + j * (8 * E_DIM));
#pragma unroll
    for (int s = 0; s < 2; s++) {
        uint32_t gs = gbase + s * GSTAGE;
#pragma unroll
        for (int i = 0; i < 4; i++)
            cp_async16(gs + gdst[i], embB + gsrc[i] + s * 256);
        CP_COMMIT();
    }
#pragma unroll
    for (int i = 0; i < 7; i++)
        if (bok[i]) cp_async16(bbase + bdst[i], bn + bsrc[i]);
    CP_COMMIT();

    // ---------------- main loop: 8 chunks ----------------
#pragma unroll
    for (int c = 0; c < 8; c++) {
        const int set = c & 1;
        if (c == 0) CP_WAIT2();         // forces G(0); B(0)/G(1) forced pre-MMA(0)
        // dot (LDS f32 gather x va regs) + convert + STS A(c) into stage c&1
        {
            char* adst = ap + set * ASTAGE + asts;
            const char* gsp = gp + set * GSTAGE + rg * 256 + l4 * 16;
#pragma unroll
            for (int j = 0; j < 4; j++) {
                float4 gv = *(const float4*)(gsp + j * (8 * 256));
                tacc[j] += va[set][j].x * gv.x + va[set][j].y * gv.y
                         + va[set][j].z * gv.z + va[set][j].w * gv.w;
                *(uint2*)(adst + j * (8 * ASTR)) = cvt_bf16x4(va[set][j]);
            }
        }
        // commit G(c+2) into stage c&1 (self-owned slots, own reads just done)
        if (c < 6) {
            uint32_t gs = gbase + set * GSTAGE;
#pragma unroll
            for (int i = 0; i < 4; i++)
                cp_async16(gs + gdst[i], embB + gsrc[i] + (c + 2) * 256);
        }
        CP_COMMIT();
        if (c < 6) {                    // input LDG chunk c+2 (2-iter cover)
            const int ko = (c + 2) * 64;
#pragma unroll
            for (int j = 0; j < 4; j++)
                va[set][j] = *(const float4*)(ipt + ko + j * (8 * E_DIM));
        }
        __syncthreads();                // A(c) visible; all warps past MMA(c-1)
        // commit B(c+1) into stage (c+1)&1 (holds B(c-1), consumed by all)
        if (c < 7) {
            uint32_t bs = bbase + ((c + 1) & 1) * BSTAGE;
            const char* bsr = bn + (c + 1) * 128;
#pragma unroll
            for (int i = 0; i < 7; i++)
                if (bok[i]) cp_async16(bs + bdst[i], bsr + bsrc[i]);
        }
        CP_COMMIT();
        CP_WAIT2();                     // forces B(c) and G(c+1)
        // MMA chunk c: A stage c&1, B stage c&1
        {
            const uint32_t ab = abase + set * ASTAGE + a_woff;
            const uint32_t bb = bbase + set * BSTAGE + b_woff;
#pragma unroll
            for (int k0 = 0; k0 < 4; k0++) {
                uint32_t a[4];
                ldmatrix_x4(a[0], a[1], a[2], a[3], ab + k0 * 32);
#pragma unroll
                for (int q = 0; q < 3; q++) {
                    uint32_t b0, b1, b2, b3;
                    ldmatrix_x4(b0, b1, b2, b3, bb + q * (16 * ASTR) + k0 * 32);
                    mma16816(acc[q * 2], a, b0, b1);
                    mma16816(acc[q * 2 + 1], a, b2, b3);
                }
                if (h == 0) {           // 7th tile (rows 48..55)
                    uint32_t b0, b1;
                    ldmatrix_x2(b0, b1, bbase + set * BSTAGE + b2_woff + k0 * 32);
                    mma16816(acc[6], a, b0, b1);
                }
            }
        }
    }

    // --- finish exact target dots (reduce over the 16 k-slot lanes) ---
#pragma unroll
    for (int j = 0; j < 4; j++) {
        float v = tacc[j];
        v += __shfl_xor_sync(0xFFFFFFFFu, v, 8);
        v += __shfl_xor_sync(0xFFFFFFFFu, v, 4);
        v += __shfl_xor_sync(0xFFFFFFFFu, v, 2);
        v += __shfl_xor_sync(0xFFFFFFFFu, v, 1);
        if (l4 == 0) s_tdot[rg + 8 * j] = v;
    }

    // --- softplus epilogue (product trick; noise x <= -1.8 always) ---
    {
        const int g = lane >> 2;
        const int tq = lane & 3;
        float plo = 1.f, phi = 1.f;
#pragma unroll
        for (int nt = 0; nt < 7; nt++) {
            if (nt < NT) {
                float c0 = cs[h * 56 + nt * 8 + 2 * tq];
                float c1 = cs[h * 56 + nt * 8 + 2 * tq + 1];
                plo *= (1.f + __expf(acc[nt][0] + c0));
                plo *= (1.f + __expf(acc[nt][1] + c1));
                phi *= (1.f + __expf(acc[nt][2] + c0));
                phi *= (1.f + __expf(acc[nt][3] + c1));
            }
        }
        float slo = __logf(plo);
        float shi = __logf(phi);
        slo += __shfl_xor_sync(0xFFFFFFFFu, slo, 1);
        slo += __shfl_xor_sync(0xFFFFFFFFu, slo, 2);
        shi += __shfl_xor_sync(0xFFFFFFFFu, shi, 1);
        shi += __shfl_xor_sync(0xFFFFFFFFu, shi, 2);
        if (tq == 0) {
            s_red[h][m0 + g] = slo;
            s_red[h][m0 + g + 8] = shi;
        }
    }
    __syncthreads();

    // --- per-row combine (+ target slot), block + grid reduce ---
    if (tid < MROWS) {
        float x0 = s_tdot[tid] + s_xc[tid];
        s_fin[tid] = s_red[0][tid] + s_red[1][tid] + softplus_exact(x0) - x0;
    }
    __syncthreads();
    if (tid < 32) {
        float s = s_fin[tid];
        s += __shfl_xor_sync(0xFFFFFFFFu, s, 16);
        s += __shfl_xor_sync(0xFFFFFFFFu, s, 8);
        s += __shfl_xor_sync(0xFFFFFFFFu, s, 4);
        s += __shfl_xor_sync(0xFFFFFFFFu, s, 2);
        s += __shfl_xor_sync(0xFFFFFFFFu, s, 1);
        if (lane == 0) {
            g_part[blockIdx.x] = s;
            __threadfence();
            int old = atomicAdd(&g_ctr, 1);
            s_flag = (old == NBLK - 1);
        }
        __syncwarp();
        if (s_flag) {
            __threadfence();
            float t = 0.f;
#pragma unroll
            for (int k = 0; k < NBLK / 32; k++)
                t += *((volatile float*)&g_part[lane + 32 * k]);
            t += __shfl_xor_sync(0xFFFFFFFFu, t, 16);
            t += __shfl_xor_sync(0xFFFFFFFFu, t, 8);
            t += __shfl_xor_sync(0xFFFFFFFFu, t, 4);
            t += __shfl_xor_sync(0xFFFFFFFFu, t, 2);
            t += __shfl_xor_sync(0xFFFFFFFFu, t, 1);
            if (lane == 0) {
                out[0] = t * (1.0f / (float)BLROWS);
                g_ctr = 0;
            }
        }
    }
}

// ---------------------------------------------------------------------------
extern "C" void kernel_launch(void* const* d_in, const int* in_sizes, int n_in,
                              void* d_out, int out_size) {
    const float* inp  = (const float*)d_in[0];
    const float* emb  = (const float*)d_in[1];
    const float* bias = (const float*)d_in[2];
    const float* lpn  = (const float*)d_in[3];
    const int*   tgt  = (const int*)  d_in[4];
    const int*   nidx = (const int*)  d_in[5];
    float* out = (float*)d_out;

    const int DSM = 128 + 2 * ASTAGE + 2 * BSTAGE + 2 * GSTAGE;  // 55680 B
    cudaFuncSetAttribute(mega_kernel, cudaFuncAttributeMaxDynamicSharedMemorySize, DSM);

    prep_kernel<<<(NPAD * 128 + 255) / 256, 256>>>(emb, nidx);
    mega_kernel<<<NBLK, 128, DSM>>>(inp, emb, bias, lpn, tgt, nidx, out);
}

// round 14
// speedup vs baseline: 1.1562x; 1.1562x over previous
#include <cuda_runtime.h>
#include <cuda_bf16.h>
#include <math.h>
#include <stdint.h>

#define E_DIM 512
#define BLROWS 16384
#define NRR 100
#define NPAD 112                        // 14 n-tiles of 8
#define NORM_TERM 10.82490511970208f    // ln(50257)
#define LOG_NR 4.605170185988092f       // ln(100)
#define MROWS 64                        // rows per CTA
#define ASTR 144                        // bf16 A-tile row stride (72 bf16)
#define ASTAGE (MROWS * ASTR)           // 9216
#define GSTAGE (MROWS * 256)            // 16384: f32 gather rows (64 x 256B)
#define NBLK 256

// B fragment table: [s(32 ksteps)][ngrp(2)][pair(4)][lane(32)] x uint4
// uint4 = {t0.b0, t0.b1, t1.b0, t1.b1} for tiles t0=grp*7+pair*2, t1=t0+1.
// pair==3 high half (t1 = grp*7+7) is zero (unused phantom tile).
__device__ __align__(16) uint4 g_bf4[32 * 2 * 4 * 32];   // 131072 B
__device__ float g_part[NBLK];
__device__ int   g_ctr = 0;             // self-resetting (graph-replay safe)

__device__ __forceinline__ uint32_t smem_u32(const void* p) {
    uint32_t a;
    asm("{ .reg .u64 t; cvta.to.shared.u64 t, %1; cvt.u32.u64 %0, t; }" : "=r"(a) : "l"(p));
    return a;
}
__device__ __forceinline__ void cp_async16(uint32_t dst, const void* src) {
    asm volatile("cp.async.cg.shared.global [%0], [%1], 16;" :: "r"(dst), "l"(src) : "memory");
}
#define CP_COMMIT() asm volatile("cp.async.commit_group;" ::: "memory")
#define CP_WAIT1()  asm volatile("cp.async.wait_group 1;" ::: "memory")
__device__ __forceinline__ void ldmatrix_x4(uint32_t& r0, uint32_t& r1,
                                            uint32_t& r2, uint32_t& r3, uint32_t addr) {
    asm volatile("ldmatrix.sync.aligned.m8n8.x4.shared.b16 {%0,%1,%2,%3}, [%4];"
                 : "=r"(r0), "=r"(r1), "=r"(r2), "=r"(r3) : "r"(addr));
}
__device__ __forceinline__ void mma16816(float* d, const uint32_t* a,
                                         uint32_t b0, uint32_t b1) {
    asm volatile("mma.sync.aligned.m16n8k16.row.col.f32.bf16.bf16.f32 "
                 "{%0,%1,%2,%3}, {%4,%5,%6,%7}, {%8,%9}, {%0,%1,%2,%3};"
                 : "+f"(d[0]), "+f"(d[1]), "+f"(d[2]), "+f"(d[3])
                 : "r"(a[0]), "r"(a[1]), "r"(a[2]), "r"(a[3]), "r"(b0), "r"(b1));
}
__device__ __forceinline__ float softplus_exact(float x) {
    return fmaxf(x, 0.0f) + log1pf(expf(-fabsf(x)));
}
__device__ __forceinline__ uint2 cvt_bf16x4(float4 v) {
    __nv_bfloat162 p0 = __float22bfloat162_rn(make_float2(v.x, v.y));
    __nv_bfloat162 p1 = __float22bfloat162_rn(make_float2(v.z, v.w));
    uint2 r;
    r.x = *reinterpret_cast<uint32_t*>(&p0);
    r.y = *reinterpret_cast<uint32_t*>(&p1);
    return r;
}

// ---------------------------------------------------------------------------
// Prep: build the B fragment table. One u32 per thread (32768 total).
// ---------------------------------------------------------------------------
__global__ void prep_kernel(const float* __restrict__ emb,
                            const int* __restrict__ nidx) {
    int u = blockIdx.x * blockDim.x + threadIdx.x;
    if (u >= 32768) return;
    int comp = u & 3;                   // {t0.b0, t0.b1, t1.b0, t1.b1}
    int e = u >> 2;
    int lane = e & 31;
    int pair = (e >> 5) & 3;
    int grp  = (e >> 7) & 1;
    int s    = e >> 8;                  // kstep 0..31
    int tile = grp * 7 + pair * 2 + (comp >> 1);
    uint32_t val = 0;
    if (!(pair == 3 && (comp >> 1) == 1)) {       // phantom tile -> zero
        int n = tile * 8 + (lane >> 2);
        if (n < NRR) {
            int k = s * 16 + (lane & 3) * 2 + (comp & 1) * 8;
            const float* src = emb + (size_t)nidx[n] * E_DIM + k;
            __nv_bfloat162 pk = __float22bfloat162_rn(make_float2(src[0], src[1]));
            val = *reinterpret_cast<uint32_t*>(&pk);
        }
    }
    reinterpret_cast<uint32_t*>(g_bf4)[e * 4 + comp] = val;
}

// ---------------------------------------------------------------------------
// Main: 64-row CTAs, 256 thr, 2/SM, one __syncthreads per chunk.
// B fragments loaded straight from the L1-hot global table (no B smem ring).
// Gather via 2-stage cp.async f32 ring (sole async stream); input via
// register prefetch depth 2; A f32->bf16 into 2-stage smem ring.
// ---------------------------------------------------------------------------
__global__ void __launch_bounds__(256, 2)
mega_kernel(const float* __restrict__ inp,
            const float* __restrict__ emb,
            const float* __restrict__ bias,
            const float* __restrict__ lpn,
            const int*   __restrict__ tgt,
            const int*   __restrict__ nidx,
            float* __restrict__ out) {
    extern __shared__ char dsm[];
    __shared__ float cs[NPAD];
    __shared__ int   s_t[MROWS];
    __shared__ float s_xc[MROWS];
    __shared__ float s_tdot[MROWS];
    __shared__ float s_red[2][MROWS];
    __shared__ float s_fin[MROWS];
    __shared__ int   s_flag;

    const int tid = threadIdx.x;
    const int lane = tid & 31;
    const int row0 = blockIdx.x * MROWS;

    const uint32_t db = smem_u32(dsm);
    const uint32_t abase = (db + 1023u) & ~1023u;
    const uint32_t gbase = abase + 2 * ASTAGE;
    char* ap = dsm + (abase - db);
    char* gp = dsm + (gbase - db);

    if (tid < NPAD) {
        int nv = (tid < NRR) ? nidx[tid] : -1;
        cs[tid] = (tid < NRR) ? (bias[nv] - NORM_TERM - lpn[nv] - LOG_NR) : -1e30f;
    }
    if (tid >= 128 && tid < 128 + MROWS) {
        int r = tid - 128;
        int t = tgt[row0 + r];
        s_t[r] = t;
        s_xc[r] = bias[t] - NORM_TERM - lpn[t] - LOG_NR;
    }
    __syncthreads();

    // ---------------- per-thread layout ----------------
    const int l4 = tid & 15;            // 16B k-slot
    const int rg = tid >> 4;            // 0..15; rows rg+16j
    const float* ipt = inp + (size_t)(row0 + rg) * E_DIM + l4 * 4;
    const uint32_t asts = (uint32_t)rg * ASTR + l4 * 8;

    // gather cp.async: op i covers (row = rg+16i, seg = l4); this thread is
    // also the sole reader of those bytes
    const char* embB = (const char*)emb;
    uint32_t gsrc[4], gdst[4];
#pragma unroll
    for (int i = 0; i < 4; i++) {
        int row = rg + 16 * i;
        gsrc[i] = (uint32_t)s_t[row] * 2048u + (uint32_t)l4 * 16u;
        gdst[i] = (uint32_t)row * 256u + (uint32_t)l4 * 16u;
    }

    // MMA fragment addressing
    const int m0 = (tid >> 5 & 3) * 16;
    const int ngrp = tid >> 7;
    const uint32_t a_woff = (uint32_t)(m0 + (lane & 15)) * ASTR + ((lane >> 4) << 4);
    const uint4* btw = g_bf4 + (size_t)ngrp * 128 + lane;   // + c*1024 + k0*256 + pair*32

    float acc[7][4];
#pragma unroll
    for (int n = 0; n < 7; n++)
#pragma unroll
        for (int j = 0; j < 4; j++) acc[n][j] = 0.f;
    float tacc[4] = {0.f, 0.f, 0.f, 0.f};

    // ---------------- prologue: G(0), G(1) ----------------
    float4 va[2][4];
#pragma unroll
    for (int s = 0; s < 2; s++)
#pragma unroll
        for (int j = 0; j < 4; j++)
            va[s][j] = *(const float4*)(ipt + s * 64 + j * (16 * E_DIM));
#pragma unroll
    for (int s = 0; s < 2; s++) {
        uint32_t gs = gbase + s * GSTAGE;
#pragma unroll
        for (int i = 0; i < 4; i++)
            cp_async16(gs + gdst[i], embB + gsrc[i] + s * 256);
        CP_COMMIT();
    }

    // ---------------- main loop: 8 chunks, ONE sync each ----------------
#pragma unroll
    for (int c = 0; c < 8; c++) {
        const int set = c & 1;
        CP_WAIT1();                     // forces G(c); G(c+1) outstanding
        // dot (LDS f32 gather x va regs) + convert + STS A(c) into stage c&1
        {
            char* adst = ap + set * ASTAGE + asts;
            const char* gsp = gp + set * GSTAGE + rg * 256 + l4 * 16;
#pragma unroll
            for (int j = 0; j < 4; j++) {
                float4 gv = *(const float4*)(gsp + j * (16 * 256));
                tacc[j] += va[set][j].x * gv.x + va[set][j].y * gv.y
                         + va[set][j].z * gv.z + va[set][j].w * gv.w;
                *(uint2*)(adst + j * (16 * ASTR)) = cvt_bf16x4(va[set][j]);
            }
        }
        if (c < 6) {                    // input LDG chunk c+2 (register, 2-iter cover)
            const int ko = (c + 2) * 64;
#pragma unroll
            for (int j = 0; j < 4; j++)
                va[set][j] = *(const float4*)(ipt + ko + j * (16 * E_DIM));
        }
        __syncthreads();                // A(c) visible; all G(c) reads complete
        // commit G(c+2) into stage c&1 (reads of this stage done by all threads)
        if (c < 6) {
            uint32_t gs = gbase + set * GSTAGE;
#pragma unroll
            for (int i = 0; i < 4; i++)
                cp_async16(gs + gdst[i], embB + gsrc[i] + (c + 2) * 256);
        }
        CP_COMMIT();                    // always (uniform group counting)
        // MMA chunk c: A from smem stage c&1, B from L1-hot fragment table
        {
            const uint32_t ab = abase + set * ASTAGE + a_woff;
            const uint4* btc = btw + (size_t)c * 1024;
#pragma unroll
            for (int k0 = 0; k0 < 4; k0++) {
                uint32_t a[4];
                ldmatrix_x4(a[0], a[1], a[2], a[3], ab + k0 * 32);
                uint4 p0 = btc[k0 * 256];
                uint4 p1 = btc[k0 * 256 + 32];
                uint4 p2 = btc[k0 * 256 + 64];
                uint4 p3 = btc[k0 * 256 + 96];
                mma16816(acc[0], a, p0.x, p0.y);
                mma16816(acc[1], a, p0.z, p0.w);
                mma16816(acc[2], a, p1.x, p1.y);
                mma16816(acc[3], a, p1.z, p1.w);
                mma16816(acc[4], a, p2.x, p2.y);
                mma16816(acc[5], a, p2.z, p2.w);
                mma16816(acc[6], a, p3.x, p3.y);
            }
        }
    }

    // --- finish exact target dots (reduce over the 16 k-slot lanes) ---
#pragma unroll
    for (int j = 0; j < 4; j++) {
        float v = tacc[j];
        v += __shfl_xor_sync(0xFFFFFFFFu, v, 8);
        v += __shfl_xor_sync(0xFFFFFFFFu, v, 4);
        v += __shfl_xor_sync(0xFFFFFFFFu, v, 2);
        v += __shfl_xor_sync(0xFFFFFFFFu, v, 1);
        if (l4 == 0) s_tdot[rg + 16 * j] = v;
    }

    // --- softplus epilogue (product trick; noise x <= -1.8 always) ---
    {
        const int g = lane >> 2;
        const int tq = lane & 3;
        float plo = 1.f, phi = 1.f;
#pragma unroll
        for (int nt = 0; nt < 7; nt++) {
            float c0 = cs[(ngrp * 7 + nt) * 8 + 2 * tq];
            float c1 = cs[(ngrp * 7 + nt) * 8 + 2 * tq + 1];
            plo *= (1.f + __expf(acc[nt][0] + c0));
            plo *= (1.f + __expf(acc[nt][1] + c1));
            phi *= (1.f + __expf(acc[nt][2] + c0));
            phi *= (1.f + __expf(acc[nt][3] + c1));
        }
        float slo = __logf(plo);
        float shi = __logf(phi);
        slo += __shfl_xor_sync(0xFFFFFFFFu, slo, 1);
        slo += __shfl_xor_sync(0xFFFFFFFFu, slo, 2);
        shi += __shfl_xor_sync(0xFFFFFFFFu, shi, 1);
        shi += __shfl_xor_sync(0xFFFFFFFFu, shi, 2);
        if (tq == 0) {
            s_red[ngrp][m0 + g] = slo;
            s_red[ngrp][m0 + g + 8] = shi;
        }
    }
    __syncthreads();

    // --- per-row combine (+ target slot), block + grid reduce ---
    if (tid < MROWS) {
        float x0 = s_tdot[tid] + s_xc[tid];
        s_fin[tid] = s_red[0][tid] + s_red[1][tid] + softplus_exact(x0) - x0;
    }
    __syncthreads();
    if (tid < 32) {
        float s = s_fin[tid] + s_fin[tid + 32];
        s += __shfl_xor_sync(0xFFFFFFFFu, s, 16);
        s += __shfl_xor_sync(0xFFFFFFFFu, s, 8);
        s += __shfl_xor_sync(0xFFFFFFFFu, s, 4);
        s += __shfl_xor_sync(0xFFFFFFFFu, s, 2);
        s += __shfl_xor_sync(0xFFFFFFFFu, s, 1);
        if (lane == 0) {
            g_part[blockIdx.x] = s;
            __threadfence();
            int old = atomicAdd(&g_ctr, 1);
            s_flag = (old == NBLK - 1);
        }
        __syncwarp();
        if (s_flag) {
            __threadfence();
            float t = 0.f;
#pragma unroll
            for (int k = 0; k < NBLK / 32; k++)
                t += *((volatile float*)&g_part[lane + 32 * k]);
            t += __shfl_xor_sync(0xFFFFFFFFu, t, 16);
            t += __shfl_xor_sync(0xFFFFFFFFu, t, 8);
            t += __shfl_xor_sync(0xFFFFFFFFu, t, 4);
            t += __shfl_xor_sync(0xFFFFFFFFu, t, 2);
            t += __shfl_xor_sync(0xFFFFFFFFu, t, 1);
            if (lane == 0) {
                out[0] = t * (1.0f / (float)BLROWS);
                g_ctr = 0;
            }
        }
    }
}

// ---------------------------------------------------------------------------
extern "C" void kernel_launch(void* const* d_in, const int* in_sizes, int n_in,
                              void* d_out, int out_size) {
    const float* inp  = (const float*)d_in[0];
    const float* emb  = (const float*)d_in[1];
    const float* bias = (const float*)d_in[2];
    const float* lpn  = (const float*)d_in[3];
    const int*   tgt  = (const int*)  d_in[4];
    const int*   nidx = (const int*)  d_in[5];
    float* out = (float*)d_out;

    const int DSM = 1024 + 2 * ASTAGE + 2 * GSTAGE;   // 52224 B -> 2 CTAs/SM
    cudaFuncSetAttribute(mega_kernel, cudaFuncAttributeMaxDynamicSharedMemorySize, DSM);

    prep_kernel<<<128, 256>>>(emb, nidx);
    mega_kernel<<<NBLK, 256, DSM>>>(inp, emb, bias, lpn, tgt, nidx, out);
}